// round 3
// baseline (speedup 1.0000x reference)
#include <cuda_runtime.h>

#define DIMS 16
#define NPTS 100
#define WSTRIDE 101
#define DBSTRIDE 100

// Precomputed per-launch scratch (allocation-free: __device__ globals).
static __device__ float g_M[DIMS * DIMS];          // inv(I - A), layout [i][j]: z_j = sum_i eps_i * M[i][j]
static __device__ float g_W[DIMS * WSTRIDE];       // exp(p[d][i]) + 0.001
static __device__ float g_DB[DIMS * DBSTRIDE];     // delta_bias cumsum

__global__ void scm_setup_kernel(const float* __restrict__ A,
                                 const float* __restrict__ p,
                                 const float* __restrict__ b) {
    const int tid = threadIdx.x;                   // 128 threads
    const float INT_LEN_F = (float)(10.0 / 99.0);

    // W table: same layout as p [16][101]
    for (int t = tid; t < DIMS * WSTRIDE; t += 128) {
        g_W[t] = expf(p[t]) + 0.001f;
    }

    // DB cumsum per dim (serial prefix, 16 threads)
    if (tid < DIMS) {
        float acc = b[tid];
        g_DB[tid * DBSTRIDE + 0] = acc;
        for (int i = 1; i < NPTS; i++) {
            acc = acc + INT_LEN_F * (expf(p[tid * WSTRIDE + i]) + 0.001f);
            g_DB[tid * DBSTRIDE + i] = acc;
        }
    }

    // Cooperative Gauss-Jordan inverse of (I - A), double precision, partial pivoting
    __shared__ double sM[DIMS][DIMS];
    __shared__ double sI[DIMS][DIMS];
    __shared__ int sPiv;

    for (int t = tid; t < DIMS * DIMS; t += 128) {
        int r = t >> 4, c = t & 15;
        sM[r][c] = (r == c ? 1.0 : 0.0) - (double)A[t];
        sI[r][c] = (r == c) ? 1.0 : 0.0;
    }
    __syncthreads();

    // Each thread owns 2 cells: (r0,c0)=(tid>>4, tid&15), (r1,c1)=(r0+8, c0)
    const int r0 = tid >> 4, c0 = tid & 15;
    const int r1 = r0 + 8,  c1 = c0;

    for (int k = 0; k < DIMS; k++) {
        if (tid == 0) {
            int piv = k; double best = fabs(sM[k][k]);
            for (int r = k + 1; r < DIMS; r++) {
                double v = fabs(sM[r][k]);
                if (v > best) { best = v; piv = r; }
            }
            sPiv = piv;
        }
        __syncthreads();
        const int piv = sPiv;
        if (tid < DIMS) {
            double t1 = sM[k][tid], t2 = sM[piv][tid];
            sM[k][tid] = t2; sM[piv][tid] = t1;
            t1 = sI[k][tid]; t2 = sI[piv][tid];
            sI[k][tid] = t2; sI[piv][tid] = t1;
        }
        __syncthreads();
        const double pv = sM[k][k];        // uniform read
        __syncthreads();                   // reads complete before scaling writes
        const double dinv = 1.0 / pv;
        if (tid < DIMS) {
            sM[k][tid] *= dinv;
            sI[k][tid] *= dinv;
        }
        __syncthreads();
        // Elimination: read phase (f from column k, pivot-row values), then write phase
        const double f0  = sM[r0][k];
        const double f1  = sM[r1][k];
        const double mk0 = sM[k][c0], ik0 = sI[k][c0];
        __syncthreads();
        if (r0 != k) { sM[r0][c0] -= f0 * mk0; sI[r0][c0] -= f0 * ik0; }
        if (r1 != k) { sM[r1][c1] -= f1 * mk0; sI[r1][c1] -= f1 * ik0; }
        __syncthreads();
    }

    for (int t = tid; t < DIMS * DIMS; t += 128) {
        int r = t >> 4, c = t & 15;
        g_M[t] = (float)sI[r][c];
    }
}

__device__ __forceinline__ float pwl_eval(float z, int j,
                                          const float* __restrict__ sW,
                                          const float* __restrict__ sDB) {
    const float VMINf = -5.0f;
    const float INT_LEN_F = (float)(10.0 / 99.0);
    const float INV_LEN_F = (float)(99.0 / 10.0);
    int idx = __float2int_rd((z - VMINf) * INV_LEN_F) + 1;
    idx = min(max(idx, 0), NPTS);
    int spi = max(idx - 1, 0);
    float w   = sW[j * WSTRIDE + idx];
    float dbv = sDB[j * DBSTRIDE + spi];
    float spv = fmaf((float)spi, INT_LEN_F, VMINf);
    return fmaf(z - spv, w, dbv);
}

__global__ __launch_bounds__(256, 2)
void scm_main_kernel(const float* __restrict__ eps, float* __restrict__ out,
                     int nPairs, int nRows) {
    __shared__ float sM[DIMS * DIMS];
    __shared__ float sW[DIMS * WSTRIDE];
    __shared__ float sDB[DIMS * DBSTRIDE];
    for (int t = threadIdx.x; t < DIMS * DIMS; t += blockDim.x)     sM[t]  = g_M[t];
    for (int t = threadIdx.x; t < DIMS * WSTRIDE; t += blockDim.x)  sW[t]  = g_W[t];
    for (int t = threadIdx.x; t < DIMS * DBSTRIDE; t += blockDim.x) sDB[t] = g_DB[t];
    __syncthreads();

    const int stride = gridDim.x * blockDim.x;
    for (int pr = blockIdx.x * blockDim.x + threadIdx.x; pr < nPairs; pr += stride) {
        const float4* src = reinterpret_cast<const float4*>(eps) + (size_t)pr * 8;

        alignas(16) float ea[DIMS];
        alignas(16) float eb[DIMS];
#pragma unroll
        for (int q = 0; q < 4; q++) {
            float4 va = __ldcs(src + q);
            float4 vb = __ldcs(src + 4 + q);
            *reinterpret_cast<float4*>(&ea[4 * q]) = va;
            *reinterpret_cast<float4*>(&eb[4 * q]) = vb;
        }

        float z0[DIMS], z1[DIMS];
#pragma unroll
        for (int j = 0; j < DIMS; j++) {
            float m = sM[j];
            z0[j] = ea[0] * m;
            z1[j] = eb[0] * m;
        }
#pragma unroll
        for (int i = 1; i < DIMS; i++) {
            const float a = ea[i], c = eb[i];
#pragma unroll
            for (int j = 0; j < DIMS; j++) {
                float m = sM[i * DIMS + j];
                z0[j] = fmaf(a, m, z0[j]);
                z1[j] = fmaf(c, m, z1[j]);
            }
        }

        alignas(16) float o0[DIMS];
        alignas(16) float o1[DIMS];
#pragma unroll
        for (int j = 0; j < DIMS; j++) {
            o0[j] = pwl_eval(z0[j], j, sW, sDB);
            o1[j] = pwl_eval(z1[j], j, sW, sDB);
        }

        float4* dst = reinterpret_cast<float4*>(out) + (size_t)pr * 8;
#pragma unroll
        for (int q = 0; q < 4; q++) {
            __stcs(dst + q,     *reinterpret_cast<float4*>(&o0[4 * q]));
            __stcs(dst + 4 + q, *reinterpret_cast<float4*>(&o1[4 * q]));
        }
    }

    // Tail: odd number of rows (not hit for B=2,000,000, kept for safety)
    if ((nRows & 1) && blockIdx.x == 0 && threadIdx.x == 0) {
        const int r = nRows - 1;
        float e[DIMS];
        for (int i = 0; i < DIMS; i++) e[i] = eps[(size_t)r * DIMS + i];
        for (int j = 0; j < DIMS; j++) {
            float z = 0.0f;
            for (int i = 0; i < DIMS; i++) z = fmaf(e[i], sM[i * DIMS + j], z);
            out[(size_t)r * DIMS + j] = pwl_eval(z, j, sW, sDB);
        }
    }
}

extern "C" void kernel_launch(void* const* d_in, const int* in_sizes, int n_in,
                              void* d_out, int out_size) {
    const float* eps = (const float*)d_in[0];
    const float* A   = (const float*)d_in[1];
    const float* p   = (const float*)d_in[2];
    const float* b   = (const float*)d_in[3];
    float* out = (float*)d_out;

    const int nRows = in_sizes[0] / DIMS;
    const int nPairs = nRows / 2;

    scm_setup_kernel<<<1, 128>>>(A, p, b);

    int grid = 592;  // 148 SMs * 2 resident blocks * 2 waves
    int maxBlocks = (nPairs + 255) / 256;
    if (maxBlocks < 1) maxBlocks = 1;
    if (grid > maxBlocks) grid = maxBlocks;
    scm_main_kernel<<<grid, 256>>>(eps, out, nPairs, nRows);
}

// round 4
// speedup vs baseline: 1.0353x; 1.0353x over previous
#include <cuda_runtime.h>

#define DIMS 16
#define NPTS 100
#define TSTRIDE 101

// Combined PWL table entry at index idx in [0,100]:
//   .x = exp(p[j][idx]) + 0.001           (the segment weight W)
//   .y = delta_bias[j][max(idx-1,0)]      (the segment base DB)
// out = (z - sp) * .x + .y, sp = VMIN + max(idx-1,0)*L

__device__ __forceinline__ float pwl_eval(float z, int j, const float2* __restrict__ sC) {
    const float VMINf = -5.0f;
    const float L     = (float)(10.0 / 99.0);
    const float INVL  = (float)(99.0 / 10.0);
    int idx = __float2int_rd((z - VMINf) * INVL) + 1;
    idx = min(max(idx, 0), NPTS);
    int spi = max(idx - 1, 0);
    float2 c = sC[j * TSTRIDE + idx];
    float sp = fmaf((float)spi, L, VMINf);
    return fmaf(z - sp, c.x, c.y);
}

__global__ __launch_bounds__(256, 2)
void scm_fused_kernel(const float* __restrict__ eps,
                      const float* __restrict__ A,
                      const float* __restrict__ p,
                      const float* __restrict__ b,
                      float* __restrict__ out,
                      int nPairs, int nRows) {
    __shared__ float2 sC[DIMS * TSTRIDE];   // 12928 B combined W/DB table
    __shared__ float4 sM4[DIMS * 4];        // 1024 B: M[i][j], 4 j's per float4
    __shared__ double gM[DIMS][DIMS];
    __shared__ double gI[DIMS][DIMS];
    __shared__ int sPiv;

    const int tid = threadIdx.x;
    const float L = (float)(10.0 / 99.0);

    // ---- Phase A: W table (all 256 threads) ----
    for (int t = tid; t < DIMS * TSTRIDE; t += 256)
        sC[t].x = expf(p[t]) + 0.001f;

    // ---- init GJ matrices while A-phase writes settle ----
    {
        int r = tid >> 4, c = tid & 15;
        gM[r][c] = (r == c ? 1.0 : 0.0) - (double)A[tid];
        gI[r][c] = (r == c) ? 1.0 : 0.0;
    }
    __syncthreads();

    // ---- Phase B: per-dim prefix scan -> DB (one warp per dim, 8 warps x 2 dims) ----
    {
        const int wid = tid >> 5, lane = tid & 31;
        for (int j = wid; j < DIMS; j += 8) {
            const float bj = b[j];
            float carry = 0.f;
#pragma unroll
            for (int ch = 0; ch < 4; ch++) {
                int i = 1 + ch * 32 + lane;                 // 1..128; valid i <= 99
                float x = (i <= NPTS - 1) ? L * sC[j * TSTRIDE + i].x : 0.f;
#pragma unroll
                for (int off = 1; off < 32; off <<= 1) {
                    float y = __shfl_up_sync(0xffffffffu, x, off);
                    if (lane >= off) x += y;
                }
                float total = __shfl_sync(0xffffffffu, x, 31);
                if (i <= NPTS - 1)
                    sC[j * TSTRIDE + i + 1].y = bj + carry + x;   // db[i] -> idx=i+1
                carry += total;
            }
            if (lane == 0) {
                sC[j * TSTRIDE + 0].y = bj;   // idx 0 -> db[0]
                sC[j * TSTRIDE + 1].y = bj;   // idx 1 -> db[0]
            }
        }
    }

    // ---- Phase C: fp64 Gauss-Jordan inverse of (I - A), 1 cell per thread ----
    {
        const int r = tid >> 4, c = tid & 15;
#pragma unroll 1
        for (int k = 0; k < DIMS; k++) {
            if (tid == 0) {
                int piv = k; double best = fabs(gM[k][k]);
                for (int rr = k + 1; rr < DIMS; rr++) {
                    double v = fabs(gM[rr][k]);
                    if (v > best) { best = v; piv = rr; }
                }
                sPiv = piv;
            }
            __syncthreads();
            const int piv = sPiv;
            if (piv != k && tid < DIMS) {
                double t1 = gM[k][tid], t2 = gM[piv][tid];
                gM[k][tid] = t2; gM[piv][tid] = t1;
                t1 = gI[k][tid]; t2 = gI[piv][tid];
                gI[k][tid] = t2; gI[piv][tid] = t1;
            }
            __syncthreads();
            const double pv = gM[k][k];
            __syncthreads();
            if (tid < DIMS) {
                const double dinv = 1.0 / pv;
                gM[k][tid] *= dinv;
                gI[k][tid] *= dinv;
            }
            __syncthreads();
            const double f  = gM[r][k];
            const double mk = gM[k][c];
            const double ik = gI[k][c];
            __syncthreads();
            if (r != k) {
                gM[r][c] -= f * mk;
                gI[r][c] -= f * ik;
            }
            __syncthreads();
        }
        // write M as float4 rows: ((float*)sM4)[i*16+j] = inv[i][j]
        reinterpret_cast<float*>(sM4)[tid] = (float)gI[r][c];
    }
    __syncthreads();

    // ---- Main streaming loop: 2 rows per thread ----
    const int stride = gridDim.x * blockDim.x;
    for (int pr = blockIdx.x * blockDim.x + tid; pr < nPairs; pr += stride) {
        const float4* src = reinterpret_cast<const float4*>(eps) + (size_t)pr * 8;

        alignas(16) float ea[DIMS];
        alignas(16) float eb[DIMS];
#pragma unroll
        for (int q = 0; q < 4; q++) {
            float4 va = __ldcs(src + q);
            float4 vb = __ldcs(src + 4 + q);
            *reinterpret_cast<float4*>(&ea[4 * q]) = va;
            *reinterpret_cast<float4*>(&eb[4 * q]) = vb;
        }

        float z0[DIMS], z1[DIMS];
#pragma unroll
        for (int q = 0; q < 4; q++) {
            float4 m = sM4[q];                       // row i=0
            z0[4*q+0] = ea[0] * m.x;  z1[4*q+0] = eb[0] * m.x;
            z0[4*q+1] = ea[0] * m.y;  z1[4*q+1] = eb[0] * m.y;
            z0[4*q+2] = ea[0] * m.z;  z1[4*q+2] = eb[0] * m.z;
            z0[4*q+3] = ea[0] * m.w;  z1[4*q+3] = eb[0] * m.w;
        }
#pragma unroll
        for (int i = 1; i < DIMS; i++) {
            const float a = ea[i], c = eb[i];
#pragma unroll
            for (int q = 0; q < 4; q++) {
                float4 m = sM4[i * 4 + q];           // LDS.128 broadcast
                z0[4*q+0] = fmaf(a, m.x, z0[4*q+0]);  z1[4*q+0] = fmaf(c, m.x, z1[4*q+0]);
                z0[4*q+1] = fmaf(a, m.y, z0[4*q+1]);  z1[4*q+1] = fmaf(c, m.y, z1[4*q+1]);
                z0[4*q+2] = fmaf(a, m.z, z0[4*q+2]);  z1[4*q+2] = fmaf(c, m.z, z1[4*q+2]);
                z0[4*q+3] = fmaf(a, m.w, z0[4*q+3]);  z1[4*q+3] = fmaf(c, m.w, z1[4*q+3]);
            }
        }

        alignas(16) float o0[DIMS];
        alignas(16) float o1[DIMS];
#pragma unroll
        for (int j = 0; j < DIMS; j++) {
            o0[j] = pwl_eval(z0[j], j, sC);
            o1[j] = pwl_eval(z1[j], j, sC);
        }

        float4* dst = reinterpret_cast<float4*>(out) + (size_t)pr * 8;
#pragma unroll
        for (int q = 0; q < 4; q++) {
            __stcs(dst + q,     *reinterpret_cast<float4*>(&o0[4 * q]));
            __stcs(dst + 4 + q, *reinterpret_cast<float4*>(&o1[4 * q]));
        }
    }

    // Tail: odd number of rows (not hit for B=2,000,000)
    if ((nRows & 1) && blockIdx.x == 0 && tid == 0) {
        const int r = nRows - 1;
        const float* Mf = reinterpret_cast<const float*>(sM4);
        float e[DIMS];
        for (int i = 0; i < DIMS; i++) e[i] = eps[(size_t)r * DIMS + i];
        for (int j = 0; j < DIMS; j++) {
            float z = 0.0f;
            for (int i = 0; i < DIMS; i++) z = fmaf(e[i], Mf[i * DIMS + j], z);
            out[(size_t)r * DIMS + j] = pwl_eval(z, j, sC);
        }
    }
}

extern "C" void kernel_launch(void* const* d_in, const int* in_sizes, int n_in,
                              void* d_out, int out_size) {
    const float* eps = (const float*)d_in[0];
    const float* A   = (const float*)d_in[1];
    const float* p   = (const float*)d_in[2];
    const float* b   = (const float*)d_in[3];
    float* out = (float*)d_out;

    const int nRows  = in_sizes[0] / DIMS;
    const int nPairs = nRows / 2;

    // One wave: 148 SMs x 2 resident blocks. Per-block setup runs once, in parallel.
    int grid = 296;
    int maxBlocks = (nPairs + 255) / 256;
    if (maxBlocks < 1) maxBlocks = 1;
    if (grid > maxBlocks) grid = maxBlocks;

    scm_fused_kernel<<<grid, 256>>>(eps, A, p, b, out, nPairs, nRows);
}

// round 8
// speedup vs baseline: 1.0553x; 1.0193x over previous
#include <cuda_runtime.h>

#define DIMS 16
#define NPTS 100
#define TSTRIDE 101

// Combined PWL table entry at index idx in [0,100]:
//   .x = exp(p[j][idx]) + 0.001           (segment weight W)
//   .y = delta_bias[j][max(idx-1,0)]      (segment base DB)
// out = (z - sp) * .x + .y, sp = VMIN + max(idx-1,0)*L

__device__ __forceinline__ float pwl_eval(float z, int j, const float2* __restrict__ sC) {
    const float VMINf = -5.0f;
    const float L     = (float)(10.0 / 99.0);
    const float INVL  = (float)(99.0 / 10.0);
    int idx = __float2int_rd((z - VMINf) * INVL) + 1;
    idx = min(max(idx, 0), NPTS);
    int spi = max(idx - 1, 0);
    float2 c = sC[j * TSTRIDE + idx];
    float sp = fmaf((float)spi, L, VMINf);
    return fmaf(z - sp, c.x, c.y);
}

__global__ __launch_bounds__(256, 4)
void scm_fused_kernel(const float* __restrict__ eps,
                      const float* __restrict__ A,
                      const float* __restrict__ p,
                      const float* __restrict__ b,
                      float* __restrict__ out,
                      int nRows) {
    __shared__ float2 sC[DIMS * TSTRIDE];   // 12928 B combined W/DB table
    __shared__ float  sMf[DIMS * DIMS];     // inv(I-A), [i][j]
    __shared__ double gM[DIMS][DIMS];
    __shared__ double gI[DIMS][DIMS];
    __shared__ int sPiv;

    const int tid = threadIdx.x;
    const float L = (float)(10.0 / 99.0);

    // ---- Phase A: W table (all 256 threads) ----
    for (int t = tid; t < DIMS * TSTRIDE; t += 256)
        sC[t].x = expf(p[t]) + 0.001f;

    // ---- init GJ matrices ----
    {
        int r = tid >> 4, c = tid & 15;
        gM[r][c] = (r == c ? 1.0 : 0.0) - (double)A[tid & 255];
        gI[r][c] = (r == c) ? 1.0 : 0.0;
    }
    __syncthreads();

    // ---- Phase B: per-dim prefix scan -> DB (one warp per dim) ----
    {
        const int wid = tid >> 5, lane = tid & 31;
        for (int j = wid; j < DIMS; j += 8) {
            const float bj = b[j];
            float carry = 0.f;
#pragma unroll
            for (int ch = 0; ch < 4; ch++) {
                int i = 1 + ch * 32 + lane;                 // 1..128; valid i <= 99
                float x = (i <= NPTS - 1) ? L * sC[j * TSTRIDE + i].x : 0.f;
#pragma unroll
                for (int off = 1; off < 32; off <<= 1) {
                    float y = __shfl_up_sync(0xffffffffu, x, off);
                    if (lane >= off) x += y;
                }
                float total = __shfl_sync(0xffffffffu, x, 31);
                if (i <= NPTS - 1)
                    sC[j * TSTRIDE + i + 1].y = bj + carry + x;   // db[i] -> idx=i+1
                carry += total;
            }
            if (lane == 0) {
                sC[j * TSTRIDE + 0].y = bj;   // idx 0 -> db[0]
                sC[j * TSTRIDE + 1].y = bj;   // idx 1 -> db[0]
            }
        }
    }

    // ---- Phase C: fp64 Gauss-Jordan inverse of (I - A), 1 cell per thread ----
    {
        const int r = tid >> 4, c = tid & 15;
#pragma unroll 1
        for (int k = 0; k < DIMS; k++) {
            if (tid == 0) {
                int piv = k; double best = fabs(gM[k][k]);
                for (int rr = k + 1; rr < DIMS; rr++) {
                    double v = fabs(gM[rr][k]);
                    if (v > best) { best = v; piv = rr; }
                }
                sPiv = piv;
            }
            __syncthreads();
            const int piv = sPiv;
            if (piv != k && tid < DIMS) {
                double t1 = gM[k][tid], t2 = gM[piv][tid];
                gM[k][tid] = t2; gM[piv][tid] = t1;
                t1 = gI[k][tid]; t2 = gI[piv][tid];
                gI[k][tid] = t2; gI[piv][tid] = t1;
            }
            __syncthreads();
            const double pv = gM[k][k];
            __syncthreads();
            if (tid < DIMS) {
                const double dinv = 1.0 / pv;
                gM[k][tid] *= dinv;
                gI[k][tid] *= dinv;
            }
            __syncthreads();
            const double f  = gM[r][k];
            const double mk = gM[k][c];
            const double ik = gI[k][c];
            __syncthreads();
            if (r != k) {
                gM[r][c] -= f * mk;
                gI[r][c] -= f * ik;
            }
            __syncthreads();
        }
        if (tid < 256) sMf[tid] = (float)gI[tid >> 4][tid & 15];
    }
    __syncthreads();

    // ---- Main loop: one output element per lane ----
    // lane = r*16 + j : r = row-within-pair (0/1), j = output dim.
    // Each warp iteration processes 4 consecutive rows (2 pairs, 256 B in / 256 B out).
    const int lane = tid & 31;
    const int r = lane >> 4;           // 0 or 1
    const int j = lane & 15;

    float Mcol[DIMS];                  // column j of M, in registers, loaded once
#pragma unroll
    for (int i = 0; i < DIMS; i++) Mcol[i] = sMf[i * DIMS + j];

    const int warpGlobal = (blockIdx.x * blockDim.x + tid) >> 5;
    const int totalWarps = (gridDim.x * blockDim.x) >> 5;
    const int nQuads = nRows >> 2;     // groups of 4 rows

    const float4* eps4 = reinterpret_cast<const float4*>(eps);

    for (int q = warpGlobal; q < nQuads; q += totalWarps) {
        // rows: 4q + r (pair 0) and 4q + 2 + r (pair 1)
        const float4* src = eps4 + (size_t)q * 16 + r * 4;

        float e0[DIMS], e1[DIMS];
#pragma unroll
        for (int k = 0; k < 4; k++) {
            float4 v0 = __ldcs(src + k);       // all 16 lanes of a row-group: same addr
            float4 v1 = __ldcs(src + 8 + k);
            e0[4*k+0] = v0.x; e0[4*k+1] = v0.y; e0[4*k+2] = v0.z; e0[4*k+3] = v0.w;
            e1[4*k+0] = v1.x; e1[4*k+1] = v1.y; e1[4*k+2] = v1.z; e1[4*k+3] = v1.w;
        }

        // two dot products, split accumulators to shorten FMA chains
        float za0 = e0[0] * Mcol[0], zb0 = e0[1] * Mcol[1];
        float za1 = e1[0] * Mcol[0], zb1 = e1[1] * Mcol[1];
#pragma unroll
        for (int i = 2; i < DIMS; i += 2) {
            za0 = fmaf(e0[i],   Mcol[i],   za0);
            zb0 = fmaf(e0[i+1], Mcol[i+1], zb0);
            za1 = fmaf(e1[i],   Mcol[i],   za1);
            zb1 = fmaf(e1[i+1], Mcol[i+1], zb1);
        }
        float z0 = za0 + zb0;
        float z1 = za1 + zb1;

        float o0 = pwl_eval(z0, j, sC);
        float o1 = pwl_eval(z1, j, sC);

        __stcs(out + (size_t)q * 64 + lane,      o0);   // coalesced 128B
        __stcs(out + (size_t)q * 64 + 32 + lane, o1);
    }

    // Tail: up to 3 leftover rows (not hit for B=2,000,000)
    if (blockIdx.x == 0 && tid == 0) {
        for (int row = nQuads * 4; row < nRows; row++) {
            float e[DIMS];
            for (int i = 0; i < DIMS; i++) e[i] = eps[(size_t)row * DIMS + i];
            for (int jj = 0; jj < DIMS; jj++) {
                float z = 0.0f;
                for (int i = 0; i < DIMS; i++) z = fmaf(e[i], sMf[i * DIMS + jj], z);
                out[(size_t)row * DIMS + jj] = pwl_eval(z, jj, sC);
            }
        }
    }
}

extern "C" void kernel_launch(void* const* d_in, const int* in_sizes, int n_in,
                              void* d_out, int out_size) {
    const float* eps = (const float*)d_in[0];
    const float* A   = (const float*)d_in[1];
    const float* p   = (const float*)d_in[2];
    const float* b   = (const float*)d_in[3];
    float* out = (float*)d_out;

    const int nRows = in_sizes[0] / DIMS;

    // One wave: 148 SMs x 4 resident blocks. Per-block setup runs once, in parallel.
    int grid = 592;
    int nQuads = nRows >> 2;
    int maxBlocks = (nQuads + 7) / 8;   // at least 1 quad per warp
    if (maxBlocks < 1) maxBlocks = 1;
    if (grid > maxBlocks) grid = maxBlocks;

    scm_fused_kernel<<<grid, 256>>>(eps, A, p, b, out, nRows);
}

// round 9
// speedup vs baseline: 1.1129x; 1.0546x over previous
#include <cuda_runtime.h>

#define DIMS 16
#define NPTS 100
#define TSTRIDE 101

// Combined PWL table entry at index idx in [0,100]:
//   .x = exp(p[j][idx]) + 0.001           (segment weight W)
//   .y = delta_bias[j][max(idx-1,0)]      (segment base DB)
// out = (z - sp) * .x + .y, sp = VMIN + max(idx-1,0)*L

__device__ __forceinline__ float pwl_eval(float z, int j, const float2* __restrict__ sC) {
    const float VMINf = -5.0f;
    const float L     = (float)(10.0 / 99.0);
    const float INVL  = (float)(99.0 / 10.0);
    int idx = __float2int_rd((z - VMINf) * INVL) + 1;
    idx = min(max(idx, 0), NPTS);
    int spi = max(idx - 1, 0);
    float2 c = sC[j * TSTRIDE + idx];
    float sp = fmaf((float)spi, L, VMINf);
    return fmaf(z - sp, c.x, c.y);
}

__global__ __launch_bounds__(256, 2)
void scm_fused_kernel(const float* __restrict__ eps,
                      const float* __restrict__ A,
                      const float* __restrict__ p,
                      const float* __restrict__ b,
                      float* __restrict__ out,
                      int nRows) {
    __shared__ __align__(16) float2 sC[DIMS * TSTRIDE];   // combined W/DB table
    __shared__ __align__(16) float  sMf[DIMS * DIMS];     // inv(I-A), [i][j]
    __shared__ double gM[DIMS][DIMS];
    __shared__ double gI[DIMS][DIMS];
    __shared__ int sPiv;

    const int tid = threadIdx.x;
    const float L = (float)(10.0 / 99.0);

    // ---- Phase A: W table (all 256 threads) ----
    for (int t = tid; t < DIMS * TSTRIDE; t += 256)
        sC[t].x = expf(p[t]) + 0.001f;

    // ---- init GJ matrices ----
    {
        int r = tid >> 4, c = tid & 15;
        gM[r][c] = (r == c ? 1.0 : 0.0) - (double)A[tid & 255];
        gI[r][c] = (r == c) ? 1.0 : 0.0;
    }
    __syncthreads();

    // ---- Phase B: per-dim prefix scan -> DB (one warp per dim) ----
    {
        const int wid = tid >> 5, lane = tid & 31;
        for (int j = wid; j < DIMS; j += 8) {
            const float bj = b[j];
            float carry = 0.f;
#pragma unroll
            for (int ch = 0; ch < 4; ch++) {
                int i = 1 + ch * 32 + lane;                 // 1..128; valid i <= 99
                float x = (i <= NPTS - 1) ? L * sC[j * TSTRIDE + i].x : 0.f;
#pragma unroll
                for (int off = 1; off < 32; off <<= 1) {
                    float y = __shfl_up_sync(0xffffffffu, x, off);
                    if (lane >= off) x += y;
                }
                float total = __shfl_sync(0xffffffffu, x, 31);
                if (i <= NPTS - 1)
                    sC[j * TSTRIDE + i + 1].y = bj + carry + x;   // db[i] -> idx=i+1
                carry += total;
            }
            if (lane == 0) {
                sC[j * TSTRIDE + 0].y = bj;   // idx 0 -> db[0]
                sC[j * TSTRIDE + 1].y = bj;   // idx 1 -> db[0]
            }
        }
    }

    // ---- Phase C: fp64 Gauss-Jordan inverse of (I - A), 1 cell per thread ----
    {
        const int r = tid >> 4, c = tid & 15;
#pragma unroll 1
        for (int k = 0; k < DIMS; k++) {
            if (tid == 0) {
                int piv = k; double best = fabs(gM[k][k]);
                for (int rr = k + 1; rr < DIMS; rr++) {
                    double v = fabs(gM[rr][k]);
                    if (v > best) { best = v; piv = rr; }
                }
                sPiv = piv;
            }
            __syncthreads();
            const int piv = sPiv;
            if (piv != k && tid < DIMS) {
                double t1 = gM[k][tid], t2 = gM[piv][tid];
                gM[k][tid] = t2; gM[piv][tid] = t1;
                t1 = gI[k][tid]; t2 = gI[piv][tid];
                gI[k][tid] = t2; gI[piv][tid] = t1;
            }
            __syncthreads();
            const double pv = gM[k][k];
            __syncthreads();
            if (tid < DIMS) {
                const double dinv = 1.0 / pv;
                gM[k][tid] *= dinv;
                gI[k][tid] *= dinv;
            }
            __syncthreads();
            const double f  = gM[r][k];
            const double mk = gM[k][c];
            const double ik = gI[k][c];
            __syncthreads();
            if (r != k) {
                gM[r][c] -= f * mk;
                gI[r][c] -= f * ik;
            }
            __syncthreads();
        }
        sMf[tid] = (float)gI[tid >> 4][tid & 15];
    }
    __syncthreads();

    // ---- Main loop: lane = (row-in-tile, j-group). 8 rows per warp iteration. ----
    // lane = r*4 + g : r = row within 8-row tile, g = output group (j = 4g..4g+3).
    // Lane holds M[:, 4g:4g+4] in 16 float4 registers -> no shared reads in loop.
    const int lane = tid & 31;
    const int g = lane & 3;
    const int r = lane >> 2;

    float4 Mr[DIMS];                   // Mr[i] = M[i][4g..4g+3]
#pragma unroll
    for (int i = 0; i < DIMS; i++)
        Mr[i] = reinterpret_cast<const float4*>(sMf)[i * 4 + g];

    const float4* eps4 = reinterpret_cast<const float4*>(eps);
    float4* out4 = reinterpret_cast<float4*>(out);

    const int warpGlobal = (blockIdx.x * blockDim.x + tid) >> 5;
    const int totalWarps = (gridDim.x * blockDim.x) >> 5;
    const int nTiles = nRows >> 3;     // 8 rows per tile

    for (int t = warpGlobal; t < nTiles; t += totalWarps) {
        const size_t rowBase4 = ((size_t)t * 8 + r) * 4;   // float4 index of this lane's row

        float e[DIMS];
#pragma unroll
        for (int k = 0; k < 4; k++) {
            float4 v = __ldcs(eps4 + rowBase4 + k);        // 4-way broadcast per address
            e[4*k+0] = v.x; e[4*k+1] = v.y; e[4*k+2] = v.z; e[4*k+3] = v.w;
        }

        // z[c] = sum_i e[i] * M[i][4g+c], 2-way split accumulators per component
        float ax = e[0] * Mr[0].x, bx = e[1] * Mr[1].x;
        float ay = e[0] * Mr[0].y, by = e[1] * Mr[1].y;
        float az = e[0] * Mr[0].z, bz = e[1] * Mr[1].z;
        float aw = e[0] * Mr[0].w, bw = e[1] * Mr[1].w;
#pragma unroll
        for (int i = 2; i < DIMS; i += 2) {
            ax = fmaf(e[i], Mr[i].x, ax);  bx = fmaf(e[i+1], Mr[i+1].x, bx);
            ay = fmaf(e[i], Mr[i].y, ay);  by = fmaf(e[i+1], Mr[i+1].y, by);
            az = fmaf(e[i], Mr[i].z, az);  bz = fmaf(e[i+1], Mr[i+1].z, bz);
            aw = fmaf(e[i], Mr[i].w, aw);  bw = fmaf(e[i+1], Mr[i+1].w, bw);
        }
        const int j0 = 4 * g;
        float4 o;
        o.x = pwl_eval(ax + bx, j0 + 0, sC);
        o.y = pwl_eval(ay + by, j0 + 1, sC);
        o.z = pwl_eval(az + bz, j0 + 2, sC);
        o.w = pwl_eval(aw + bw, j0 + 3, sC);

        __stcs(out4 + rowBase4 + g, o);                    // fully coalesced 512B/warp
    }

    // Tail: up to 7 leftover rows (not hit for B=2,000,000)
    if (blockIdx.x == 0 && tid == 0) {
        for (int row = nTiles * 8; row < nRows; row++) {
            float e[DIMS];
            for (int i = 0; i < DIMS; i++) e[i] = eps[(size_t)row * DIMS + i];
            for (int jj = 0; jj < DIMS; jj++) {
                float z = 0.0f;
                for (int i = 0; i < DIMS; i++) z = fmaf(e[i], sMf[i * DIMS + jj], z);
                out[(size_t)row * DIMS + jj] = pwl_eval(z, jj, sC);
            }
        }
    }
}

extern "C" void kernel_launch(void* const* d_in, const int* in_sizes, int n_in,
                              void* d_out, int out_size) {
    const float* eps = (const float*)d_in[0];
    const float* A   = (const float*)d_in[1];
    const float* p   = (const float*)d_in[2];
    const float* b   = (const float*)d_in[3];
    float* out = (float*)d_out;

    const int nRows = in_sizes[0] / DIMS;

    // One wave: 148 SMs x 2 resident blocks. Per-block setup runs once, in parallel.
    int grid = 296;
    int nTiles = nRows >> 3;
    int maxBlocks = (nTiles + 7) / 8;
    if (maxBlocks < 1) maxBlocks = 1;
    if (grid > maxBlocks) grid = maxBlocks;

    scm_fused_kernel<<<grid, 256>>>(eps, A, p, b, out, nRows);
}